// round 2
// baseline (speedup 1.0000x reference)
#include <cuda_runtime.h>
#include <cstdint>
#include <cstddef>

#define NN  50000
#define NE  800000
#define CH  512
#define CH4 128   // CH/4 float4 per row
#define BM  64
#define BK  8

// ---------------- scratch (device globals: allocation-free rule) -------------
__device__ int   g_cnt[2][NN];
__device__ float g_dis[2][NN];
__device__ int   g_rowptr[2][NN + 1];
__device__ int   g_cursor[2][NN];
__device__ int   g_src[2][NE];
__device__ __align__(16) float g_bufA[(size_t)NN * CH];
__device__ __align__(16) float g_bufB[(size_t)NN * CH];

// ---------------- graph preprocessing ---------------------------------------
__global__ void reset_kernel() {
    int i = blockIdx.x * blockDim.x + threadIdx.x;
    if (i < 2 * NN) ((int*)g_cnt)[i] = 0;
}

// edge_index delivered as int32 (harness dtype contract: f32/i32/bf16 only)
__global__ void count_kernel(const int* __restrict__ ei, int g) {
    int e = blockIdx.x * blockDim.x + threadIdx.x;
    if (e < NE) {
        int c = ei[NE + e];
        if ((unsigned)c < (unsigned)NN) atomicAdd(&g_cnt[g][c], 1);
    }
}

__global__ void dis_kernel() {
    int i = blockIdx.x * blockDim.x + threadIdx.x;
    if (i < NN) {
        g_dis[0][i] = rsqrtf((float)g_cnt[0][i] + 1.0f);  // +1 self loop
        g_dis[1][i] = rsqrtf((float)g_cnt[1][i] + 1.0f);
    }
}

// one block per graph: chunked Hillis-Steele exclusive scan of in-degree counts
__global__ void scan_kernel() {
    int g = blockIdx.x;
    __shared__ int sh[1024];
    __shared__ int carry;
    int t = threadIdx.x;
    if (t == 0) carry = 0;
    __syncthreads();
    for (int base = 0; base < NN; base += 1024) {
        int i = base + t;
        int v = (i < NN) ? g_cnt[g][i] : 0;
        sh[t] = v;
        __syncthreads();
        for (int off = 1; off < 1024; off <<= 1) {
            int u = (t >= off) ? sh[t - off] : 0;
            __syncthreads();
            sh[t] += u;
            __syncthreads();
        }
        int excl = sh[t] - v;
        if (i < NN) {
            int o = carry + excl;
            g_rowptr[g][i] = o;
            g_cursor[g][i] = o;
        }
        __syncthreads();
        if (t == 1023) carry += sh[1023];
        __syncthreads();
    }
    if (t == 0) g_rowptr[g][NN] = carry;
}

__global__ void scatter_kernel(const int* __restrict__ ei, int g) {
    int e = blockIdx.x * blockDim.x + threadIdx.x;
    if (e < NE) {
        int r = ei[e];
        int c = ei[NE + e];
        if ((unsigned)r < (unsigned)NN && (unsigned)c < (unsigned)NN) {
            int pos = atomicAdd(&g_cursor[g][c], 1);
            g_src[g][pos] = r;
        }
    }
}

// ---------------- SpMM: h_out[i] = dis_i^2*h[i] + sum_j dis_i*dis_src*h[src] -
__global__ __launch_bounds__(128) void spmm_kernel(
    int g, const float4* __restrict__ in, float4* __restrict__ out) {
    int i = blockIdx.x;
    int t = threadIdx.x;  // 0..127, owns 4 channels
    const int*   __restrict__ src = g_src[g];
    const float* __restrict__ dis = g_dis[g];
    float di = dis[i];
    int beg = g_rowptr[g][i];
    int end = g_rowptr[g][i + 1];
    float4 h = in[(size_t)i * CH4 + t];
    float ws = di * di;  // self loop weight
    float4 acc = make_float4(h.x * ws, h.y * ws, h.z * ws, h.w * ws);
    for (int j = beg; j < end; ++j) {
        int s = src[j];
        float w = di * dis[s];
        float4 v = in[(size_t)s * CH4 + t];
        acc.x = fmaf(w, v.x, acc.x);
        acc.y = fmaf(w, v.y, acc.y);
        acc.z = fmaf(w, v.z, acc.z);
        acc.w = fmaf(w, v.w, acc.w);
    }
    out[(size_t)i * CH4 + t] = acc;
}

// ---------------- fused GEMM (f32x2 packed FMA) + softmax + argmax -----------
// 512 threads: cg = tid&63 owns 8 consecutive cols, rg = tid>>6 owns 8 rows.
// Phase-1 tiles (shW 16KB + shH 4.2KB) and phase-2 reduction scratch
// (red+redi 33.3KB) share one overlaid smem buffer -> 33.3KB static total.
#define FMA2(d, a, b) \
    asm("fma.rn.f32x2 %0, %1, %2, %0;" : "+l"(d) : "l"(a), "l"(b))
#define AV(r, j) av[(r)][(j)]

#define SMEM_BYTES 33280  // max(16384+4224, 2*64*65*4)

__global__ __launch_bounds__(512) void gemm_softmax_kernel(
    const float* __restrict__ Hm, const float* __restrict__ Wm,
    const float* __restrict__ Bv, float* __restrict__ out,
    float* __restrict__ pred, size_t out_lim) {
    __shared__ __align__(16) unsigned char smem[SMEM_BYTES];
    __shared__ float rowmax[BM];
    __shared__ float rowinv[BM];
    __shared__ int   rowarg[BM];

    // phase-1 views
    float (*shW)[CH] = (float(*)[CH])smem;                                  // 16384 B
    unsigned long long (*shH)[BM + 2] =
        (unsigned long long(*)[BM + 2])(smem + 16384);                      // 4224 B
    // phase-2 views (overlay)
    float (*red)[65]  = (float(*)[65])smem;                                 // 16640 B
    int   (*redi)[65] = (int(*)[65])(smem + 16640);                         // 16640 B

    int tid = threadIdx.x;
    int cg = tid & 63;
    int rg = tid >> 6;
    int row0 = blockIdx.x * BM;

    unsigned long long acc[8][4];
#pragma unroll
    for (int r = 0; r < 8; ++r)
#pragma unroll
        for (int p = 0; p < 4; ++p) acc[r][p] = 0ULL;

    int hrow = tid >> 3;  // 0..63
    int hkk  = tid & 7;
    int hgr  = row0 + hrow;
    bool hvalid = (hgr < NN);
    const float* hptr = &Hm[(size_t)(hvalid ? hgr : 0) * CH + hkk];

    for (int k0 = 0; k0 < CH; k0 += BK) {
        // W tile 8x512: 2 float4 per thread, coalesced
#pragma unroll
        for (int rr = 0; rr < 2; ++rr) {
            int idx = tid + rr * 512;
            int kr = idx >> 7;
            int c4 = (idx & 127) << 2;
            *(float4*)&shW[kr][c4] =
                *(const float4*)&Wm[(size_t)(k0 + kr) * CH + c4];
        }
        // h tile, stored transposed + duplicated ((v,v) packed in 64 bits)
        {
            float v = hvalid ? hptr[k0] : 0.0f;
            unsigned long long d = (unsigned long long)__float_as_uint(v);
            d |= d << 32;
            shH[hkk][hrow] = d;
        }
        __syncthreads();
#pragma unroll
        for (int k = 0; k < BK; ++k) {
            const ulonglong2* wp = (const ulonglong2*)&shW[k][cg << 3];
            ulonglong2 w01 = wp[0];
            ulonglong2 w23 = wp[1];
            unsigned long long wv0 = w01.x, wv1 = w01.y, wv2 = w23.x, wv3 = w23.y;
            const ulonglong2* hp = (const ulonglong2*)&shH[k][rg << 3];
            ulonglong2 hA = hp[0], hB = hp[1], hC = hp[2], hD = hp[3];
            unsigned long long hv[8] = {hA.x, hA.y, hB.x, hB.y,
                                        hC.x, hC.y, hD.x, hD.y};
#pragma unroll
            for (int r = 0; r < 8; ++r) {
                FMA2(acc[r][0], hv[r], wv0);
                FMA2(acc[r][1], hv[r], wv1);
                FMA2(acc[r][2], hv[r], wv2);
                FMA2(acc[r][3], hv[r], wv3);
            }
        }
        __syncthreads();  // also fences phase-1 tile reads before red overlay
    }

    // unpack + bias
    float bc[8];
#pragma unroll
    for (int j = 0; j < 8; ++j) bc[j] = Bv[(cg << 3) + j];
    float av[8][8];
#pragma unroll
    for (int r = 0; r < 8; ++r)
#pragma unroll
        for (int p = 0; p < 4; ++p) {
            unsigned long long v = acc[r][p];
            av[r][2 * p]     = __uint_as_float((unsigned)v) + bc[2 * p];
            av[r][2 * p + 1] = __uint_as_float((unsigned)(v >> 32)) + bc[2 * p + 1];
        }

    // phase A: row max + argmax (first-max semantics via strict >)
#pragma unroll
    for (int r = 0; r < 8; ++r) {
        float m = AV(r, 0);
        int ai = 0;
#pragma unroll
        for (int j = 1; j < 8; ++j) {
            float v = AV(r, j);
            if (v > m) { m = v; ai = j; }
        }
        int lr = (rg << 3) + r;
        red[lr][cg]  = m;
        redi[lr][cg] = (cg << 3) + ai;
    }
    __syncthreads();
    if (tid < BM) {
        float m = red[tid][0];
        int ai = redi[tid][0];
        for (int j = 1; j < 64; ++j) {
            float v = red[tid][j];
            if (v > m) { m = v; ai = redi[tid][j]; }
        }
        rowmax[tid] = m;
        rowarg[tid] = ai;
    }
    __syncthreads();

    // phase B: exp + row sum
#pragma unroll
    for (int r = 0; r < 8; ++r) {
        int lr = (rg << 3) + r;
        float m = rowmax[lr];
        float s = 0.0f;
#pragma unroll
        for (int j = 0; j < 8; ++j) {
            float e = __expf(AV(r, j) - m);
            AV(r, j) = e;
            s += e;
        }
        red[lr][cg] = s;
    }
    __syncthreads();
    if (tid < BM) {
        float s = 0.0f;
        for (int j = 0; j < 64; ++j) s += red[tid][j];
        rowinv[tid] = 1.0f / s;
    }
    __syncthreads();

    // write softmax (guarded by out_lim)
#pragma unroll
    for (int r = 0; r < 8; ++r) {
        int lr = (rg << 3) + r;
        int gr = row0 + lr;
        if (gr < NN) {
            size_t base = (size_t)gr * CH + (cg << 3);
            if (base + 8 <= out_lim) {
                float inv = rowinv[lr];
                float4 o0 = make_float4(AV(r, 0) * inv, AV(r, 1) * inv,
                                        AV(r, 2) * inv, AV(r, 3) * inv);
                float4 o1 = make_float4(AV(r, 4) * inv, AV(r, 5) * inv,
                                        AV(r, 6) * inv, AV(r, 7) * inv);
                *(float4*)&out[base]     = o0;
                *(float4*)&out[base + 4] = o1;
            }
        }
    }
    if (pred != nullptr && tid < BM && row0 + tid < NN) {
        size_t pidx = (size_t)(pred - out) + (row0 + tid);
        if (pidx < out_lim) pred[row0 + tid] = (float)rowarg[tid];
    }
}

// ---------------- launch -----------------------------------------------------
extern "C" void kernel_launch(void* const* d_in, const int* in_sizes, int n_in,
                              void* d_out, int out_size) {
    const float* x  = (const float*)d_in[0];
    const int*   e1 = (const int*)d_in[1];
    const int*   e2 = (const int*)d_in[2];
    const float* W1 = (const float*)d_in[3];
    const float* b1 = (const float*)d_in[4];
    const float* W2 = (const float*)d_in[5];
    const float* b2 = (const float*)d_in[6];

    float* out = (float*)d_out;
    float* logits1 = out;
    float* logits2 = out + (size_t)NN * CH;
    float* preds   = out + 2 * (size_t)NN * CH;
    size_t out_lim = (size_t)out_size;

    float *bufA, *bufB;
    cudaGetSymbolAddress((void**)&bufA, g_bufA);
    cudaGetSymbolAddress((void**)&bufB, g_bufB);

    reset_kernel<<<(2 * NN + 255) / 256, 256>>>();
    count_kernel<<<(NE + 255) / 256, 256>>>(e1, 0);
    count_kernel<<<(NE + 255) / 256, 256>>>(e2, 1);
    dis_kernel<<<(NN + 255) / 256, 256>>>();
    scan_kernel<<<2, 1024>>>();
    scatter_kernel<<<(NE + 255) / 256, 256>>>(e1, 0);
    scatter_kernel<<<(NE + 255) / 256, 256>>>(e2, 1);

    int gblocks = (NN + BM - 1) / BM;

    // conv 1
    spmm_kernel<<<NN, 128>>>(0, (const float4*)x,    (float4*)bufA);
    spmm_kernel<<<NN, 128>>>(0, (const float4*)bufA, (float4*)bufB);
    gemm_softmax_kernel<<<gblocks, 512>>>(bufB, W1, b1, logits1, preds, out_lim);

    // conv 2
    spmm_kernel<<<NN, 128>>>(1, (const float4*)x,    (float4*)bufA);
    spmm_kernel<<<NN, 128>>>(1, (const float4*)bufA, (float4*)bufB);
    gemm_softmax_kernel<<<gblocks, 512>>>(bufB, W2, b2, logits2, nullptr, out_lim);
}